// round 9
// baseline (speedup 1.0000x reference)
#include <cuda_runtime.h>
#include <cstdint>

// TinyLSTM: B=64, T=2048, H=256, V=256
// out = [ logits (64*2048*256) | h_n (64*256) | c_n (64*256) ]  (float32)

#define T_SEQ 2048
#define BATCH 64
#define HID   256
#define G4    1024
#define VOCAB 256
#define LOGITS_ELEMS (BATCH * T_SEQ * HID)

#define NG 16          // batch groups (4 batches each)
#define NS 16          // gate slices per group (16 j-columns x 4 gates = 64 rows)
#define HP2 132        // skewed k-chunk stride (floats): kq at kq*132 -> disjoint banks

// scratch (static device arrays; no allocation)
__device__ float g_xtab[VOCAB * G4];   // [v][r] = W_ih[r][v] + b_ih[r] + b_hh[r]
__device__ float g_fcwt[HID * VOCAB];  // [k][c] = fc_W[c][k]
__device__ __align__(64) unsigned g_flag[NG][NS];  // [group][slice] = steps published

// ---- packed f32x2 helpers ----
__device__ __forceinline__ unsigned long long pk2(float a, float b) {
    unsigned long long r;
    asm("mov.b64 %0, {%1, %2};" : "=l"(r) : "f"(a), "f"(b));
    return r;
}
__device__ __forceinline__ void upk2(unsigned long long v, float& a, float& b) {
    asm("mov.b64 {%0, %1}, %2;" : "=f"(a), "=f"(b) : "l"(v));
}
__device__ __forceinline__ void ffma2(unsigned long long& d, unsigned long long a, unsigned long long b) {
    asm("fma.rn.f32x2 %0, %1, %2, %0;" : "+l"(d) : "l"(a), "l"(b));
}
__device__ __forceinline__ float4 ldcg4(const float* p) {
    float4 v;
    asm volatile("ld.global.cg.v4.f32 {%0,%1,%2,%3}, [%4];"
                 : "=f"(v.x), "=f"(v.y), "=f"(v.z), "=f"(v.w) : "l"(p));
    return v;
}
__device__ __forceinline__ uint4 ld_acq4(const unsigned* p) {
    uint4 v;
    asm volatile("ld.acquire.gpu.global.v4.u32 {%0,%1,%2,%3}, [%4];"
                 : "=r"(v.x), "=r"(v.y), "=r"(v.z), "=r"(v.w) : "l"(p) : "memory");
    return v;
}
__device__ __forceinline__ void st_rel(unsigned* p, unsigned v) {
    asm volatile("st.release.gpu.global.u32 [%0], %1;" :: "l"(p), "r"(v) : "memory");
}
__device__ __forceinline__ void bar_named(int id) {
    asm volatile("bar.sync %0, 128;" :: "r"(id) : "memory");
}

// =====================================================================
// Phase 0: token table (biases folded), fc_W transpose, zero flags
// =====================================================================
__global__ void prep_kernel(const float* __restrict__ W_ih,
                            const float* __restrict__ b_ih,
                            const float* __restrict__ b_hh,
                            const float* __restrict__ fc_W) {
    int idx = blockIdx.x * blockDim.x + threadIdx.x;
    if (idx < VOCAB * G4) {
        int v = idx >> 10;
        int r = idx & 1023;
        g_xtab[v * G4 + r] = W_ih[r * VOCAB + v] + b_ih[r] + b_hh[r];
    }
    if (idx < HID * VOCAB) {
        int k = idx >> 8;
        int c = idx & 255;
        g_fcwt[k * VOCAB + c] = fc_W[c * HID + k];
    }
    if (idx < NG * NS) ((unsigned*)g_flag)[idx] = 0u;
}

// =====================================================================
// Phase 1: persistent LSTM with dual independent half-CTA engines.
// 16 groups x 4 batches; 16 slices (64 gate rows) per group. CTA c
// (q=c>>3, d=c&7) hosts half 0 = (group q, slice d) and half 1 =
// (group (q+8)&15, slice d+8): DIFFERENT groups -> independent timing.
// Each half: 128 threads = 64 rows x 2 k-chunks; W_hh slice in regs
// (w2[64] = 128 regs). Named barriers (id 1/2) per half; h exchanged
// through the hs region of d_out with a release/acquire flag array.
// While one half waits on its group's flags, the other half's warps
// own the SMSP issue slots -> exchange latency hidden.
// =====================================================================
__global__ void __launch_bounds__(256, 1)
lstm_kernel(const int* __restrict__ x,
            const float* __restrict__ W_hh,
            float* __restrict__ out) {
    __shared__ __align__(16) float sh_h[2][4][2 * HP2];  // [half][batch][chunk*HP2+k]
    __shared__ float sh_g[2][64][5];                     // [half][row][batch], stride-5
    __shared__ int   sh_tok[2][2][4];                    // [half][phase][batch]

    const int c   = blockIdx.x;
    const int qq  = c >> 3, d = c & 7;
    const int tid = threadIdx.x;
    const int hid = tid >> 7;                 // half 0/1
    const int ht  = tid & 127;                // thread-in-half
    const int grp = hid ? ((qq + 8) & 15) : qq;
    const int slc = hid ? (d + 8) : d;
    const int b_base = grp * 4;
    const int barid  = 1 + hid;

    const int rr   = ht >> 1;                 // local row 0..63
    const int kq   = ht & 1;                  // k-chunk 0..1 (128 k each)
    const int gate = rr >> 4;
    const int jj   = rr & 15;
    const int r_global = gate * 256 + slc * 16 + jj;

    // --- W_hh slice -> registers as f32x2 (64 regs-pairs = 128 regs) ---
    unsigned long long w2[64];
    {
        const float4* wr = reinterpret_cast<const float4*>(
            W_hh + (size_t)r_global * HID + kq * 128);
#pragma unroll
        for (int i = 0; i < 32; i++) {
            float4 v = wr[i];
            w2[2 * i]     = pk2(v.x, v.y);
            w2[2 * i + 1] = pk2(v.z, v.w);
        }
    }
    float creg = 0.0f;                        // cell state for epilogue threads
    if (ht < 4) sh_tok[hid][0][ht] = x[(size_t)(b_base + ht) * T_SEQ] & 255;
    __syncthreads();                          // one-time init fence (both halves)

    float* hsout = out;                                 // [B][T][H]
    float* hN    = out + (size_t)LOGITS_ELEMS;          // [B][H]
    float* cN    = hN + BATCH * HID;                    // [B][H]

    for (int t = 0; t < T_SEQ; t++) {
        const int pb = t & 1;

        // ---- token-table contributions (issued early, consumed late) ----
        float xg0 = 0.f, xg1 = 0.f, xg2 = 0.f, xg3 = 0.f;
        if (kq == 0) {
            xg0 = __ldg(&g_xtab[sh_tok[hid][pb][0] * G4 + r_global]);
            xg1 = __ldg(&g_xtab[sh_tok[hid][pb][1] * G4 + r_global]);
            xg2 = __ldg(&g_xtab[sh_tok[hid][pb][2] * G4 + r_global]);
            xg3 = __ldg(&g_xtab[sh_tok[hid][pb][3] * G4 + r_global]);
        }
        // prefetch next tokens (off critical path)
        if (ht < 4 && t + 1 < T_SEQ)
            sh_tok[hid][pb ^ 1][ht] = x[(size_t)(b_base + ht) * T_SEQ + t + 1] & 255;

        // ---- self-poll: every thread waits for all 16 slices of h(t-1) ----
        if (t > 0) {
            const unsigned tt = (unsigned)t;
            for (;;) {
                uint4 f0 = ld_acq4(&g_flag[grp][0]);
                uint4 f1 = ld_acq4(&g_flag[grp][4]);
                uint4 f2 = ld_acq4(&g_flag[grp][8]);
                uint4 f3 = ld_acq4(&g_flag[grp][12]);
                unsigned mn = min(min(min(f0.x, f0.y), min(f0.z, f0.w)),
                                  min(min(f1.x, f1.y), min(f1.z, f1.w)));
                mn = min(mn, min(min(min(f2.x, f2.y), min(f2.z, f2.w)),
                                 min(min(f3.x, f3.y), min(f3.z, f3.w))));
                if (mn >= tt) break;
            }
        }

        // ---- load h(t-1) into skewed smem (acquire above orders these) ----
#pragma unroll
        for (int i = 0; i < 2; i++) {
            int idx = ht + 128 * i;           // 0..255 -> 4 batches x 64 float4
            int b = idx >> 6, k4 = idx & 63;
            float4 hv;
            if (t == 0) hv = make_float4(0.f, 0.f, 0.f, 0.f);
            else hv = ldcg4(&hsout[((size_t)(b_base + b) * T_SEQ + (t - 1)) * HID + k4 * 4]);
            *reinterpret_cast<float4*>(
                &sh_h[hid][b][(k4 >> 5) * HP2 + (k4 & 31) * 4]) = hv;
        }
        bar_named(barid);

        // ---- dot products: 4 batches x 128 k, weights in registers ----
        float accf[4];
#pragma unroll
        for (int b = 0; b < 4; b++) {
            unsigned long long a2 = 0ull, b2 = 0ull;
            const ulonglong2* hp =
                reinterpret_cast<const ulonglong2*>(&sh_h[hid][b][kq * HP2]);
#pragma unroll
            for (int i = 0; i < 32; i++) {
                ulonglong2 hv = hp[i];
                ffma2(a2, w2[2 * i],     hv.x);
                ffma2(b2, w2[2 * i + 1], hv.y);
            }
            float a0, a1, c0, c1;
            upk2(a2, a0, a1);
            upk2(b2, c0, c1);
            accf[b] = (a0 + a1) + (c0 + c1);
        }
        // reduce across the 2 k-chunks (adjacent lanes), lane kq=0 stores
#pragma unroll
        for (int b = 0; b < 4; b++)
            accf[b] += __shfl_xor_sync(0xffffffffu, accf[b], 1);
        if (kq == 0) {
            sh_g[hid][rr][0] = accf[0] + xg0;
            sh_g[hid][rr][1] = accf[1] + xg1;
            sh_g[hid][rr][2] = accf[2] + xg2;
            sh_g[hid][rr][3] = accf[3] + xg3;
        }
        bar_named(barid);

        // ---- gate nonlinearities + state update (64 threads/half) ----
        if (ht < 64) {
            int b = ht >> 4, j = ht & 15;
            float iv = sh_g[hid][     j][b];
            float fv = sh_g[hid][16 + j][b];
            float gv = sh_g[hid][32 + j][b];
            float ov = sh_g[hid][48 + j][b];
            float is = __fdividef(1.f, 1.f + __expf(-iv));
            float fs = __fdividef(1.f, 1.f + __expf(-fv));
            float gt = 1.f - __fdividef(2.f, 1.f + __expf(2.f * gv));
            float os = __fdividef(1.f, 1.f + __expf(-ov));
            creg = fs * creg + is * gt;
            float ct = 1.f - __fdividef(2.f, 1.f + __expf(2.f * creg));
            float hv = os * ct;
            hsout[((size_t)(b_base + b) * T_SEQ + t) * HID + slc * 16 + j] = hv;
            if (t == T_SEQ - 1) {
                hN[(b_base + b) * HID + slc * 16 + j] = hv;
                cN[(b_base + b) * HID + slc * 16 + j] = creg;
            }
        }
        bar_named(barid);                     // all h stores cta-ordered
        if (ht == 0) st_rel(&g_flag[grp][slc], (unsigned)(t + 1));
    }
}

// =====================================================================
// Phase 2: logits = hs @ fc_W^T + fc_b, in-place over the hs region.
// Each CTA: 32 rows, 128 threads, 8x8 register tile per thread, f32x2.
// =====================================================================
#define FC_KSLAB 32
#define FC_WPAD  260

__global__ void __launch_bounds__(128)
fc_kernel(float* __restrict__ out, const float* __restrict__ fc_b) {
    __shared__ __align__(16) float wslab[FC_KSLAB][FC_WPAD];  // ~33 KB
    __shared__ float sh_h[32][FC_KSLAB + 1];                  // 4.1 KB

    const int tid = threadIdx.x;
    const int rg  = tid >> 5;
    const int cg  = tid & 31;
    const size_t row_base = (size_t)blockIdx.x * 32;

    unsigned long long acc[8][4];
#pragma unroll
    for (int a = 0; a < 8; a++)
#pragma unroll
        for (int b = 0; b < 4; b++) acc[a][b] = 0ull;

    for (int k0 = 0; k0 < HID; k0 += FC_KSLAB) {
        __syncthreads();
        for (int i = tid; i < FC_KSLAB * 64; i += 128) {
            int kk = i >> 6, c4 = i & 63;
            *reinterpret_cast<float4*>(&wslab[kk][c4 * 4]) =
                *reinterpret_cast<const float4*>(&g_fcwt[(size_t)(k0 + kk) * VOCAB + c4 * 4]);
        }
        for (int i = tid; i < 32 * (FC_KSLAB / 4); i += 128) {
            int rr = i >> 3, k4 = i & 7;
            float4 v = *reinterpret_cast<const float4*>(
                &out[(row_base + rr) * HID + k0 + k4 * 4]);
            sh_h[rr][k4 * 4 + 0] = v.x;
            sh_h[rr][k4 * 4 + 1] = v.y;
            sh_h[rr][k4 * 4 + 2] = v.z;
            sh_h[rr][k4 * 4 + 3] = v.w;
        }
        __syncthreads();
#pragma unroll 4
        for (int kk = 0; kk < FC_KSLAB; kk++) {
            ulonglong2 wv0 = *reinterpret_cast<const ulonglong2*>(&wslab[kk][cg * 8]);
            ulonglong2 wv1 = *reinterpret_cast<const ulonglong2*>(&wslab[kk][cg * 8 + 4]);
#pragma unroll
            for (int rr = 0; rr < 8; rr++) {
                float hv = sh_h[rg * 8 + rr][kk];
                unsigned long long hp = pk2(hv, hv);
                ffma2(acc[rr][0], hp, wv0.x);
                ffma2(acc[rr][1], hp, wv0.y);
                ffma2(acc[rr][2], hp, wv1.x);
                ffma2(acc[rr][3], hp, wv1.y);
            }
        }
    }

    float bias[8];
#pragma unroll
    for (int cc = 0; cc < 8; cc++) bias[cc] = fc_b[cg * 8 + cc];
#pragma unroll
    for (int rr = 0; rr < 8; rr++) {
        float v[8];
        upk2(acc[rr][0], v[0], v[1]);
        upk2(acc[rr][1], v[2], v[3]);
        upk2(acc[rr][2], v[4], v[5]);
        upk2(acc[rr][3], v[6], v[7]);
        float4 o0 = make_float4(v[0] + bias[0], v[1] + bias[1], v[2] + bias[2], v[3] + bias[3]);
        float4 o1 = make_float4(v[4] + bias[4], v[5] + bias[5], v[6] + bias[6], v[7] + bias[7]);
        float* dst = out + (row_base + rg * 8 + rr) * VOCAB + cg * 8;
        *reinterpret_cast<float4*>(dst)     = o0;
        *reinterpret_cast<float4*>(dst + 4) = o1;
    }
}

// =====================================================================
extern "C" void kernel_launch(void* const* d_in, const int* in_sizes, int n_in,
                              void* d_out, int out_size) {
    (void)in_sizes; (void)n_in; (void)out_size;
    const int*   x      = (const int*)d_in[0];     // int32 tokens
    const float* W_ih   = (const float*)d_in[1];
    const float* W_hh   = (const float*)d_in[2];
    const float* b_ih   = (const float*)d_in[3];
    const float* b_hh   = (const float*)d_in[4];
    const float* fc_W   = (const float*)d_in[5];
    const float* fc_b   = (const float*)d_in[6];
    float* out = (float*)d_out;

    prep_kernel<<<1024, 256>>>(W_ih, b_ih, b_hh, fc_W);
    lstm_kernel<<<128, 256>>>(x, W_hh, out);
    fc_kernel<<<(BATCH * T_SEQ) / 32, 128>>>(out, fc_b);
}

// round 10
// speedup vs baseline: 1.4863x; 1.4863x over previous
#include <cuda_runtime.h>
#include <cstdint>

// TinyLSTM: B=64, T=2048, H=256, V=256
// out = [ logits (64*2048*256) | h_n (64*256) | c_n (64*256) ]  (float32)

#define T_SEQ 2048
#define BATCH 64
#define HID   256
#define G4    1024
#define VOCAB 256

#define LOGITS_ELEMS (BATCH * T_SEQ * HID)

#define HPAD 132   // skewed chunk stride (floats): chunk q at q*132 -> disjoint banks

// scratch (static device arrays; no allocation)
__device__ float g_xtab[VOCAB * G4];   // [v][r] = W_ih[r][v] + b_ih[r] + b_hh[r]
__device__ float g_fcwt[HID * VOCAB];  // [k][c] = fc_W[c][k]
__device__ __align__(32) unsigned g_flag[16][8];  // [group][slice] = steps published

// ---- packed f32x2 helpers ----
__device__ __forceinline__ unsigned long long pk2(float a, float b) {
    unsigned long long r;
    asm("mov.b64 %0, {%1, %2};" : "=l"(r) : "f"(a), "f"(b));
    return r;
}
__device__ __forceinline__ void upk2(unsigned long long v, float& a, float& b) {
    asm("mov.b64 {%0, %1}, %2;" : "=f"(a), "=f"(b) : "l"(v));
}
__device__ __forceinline__ void ffma2(unsigned long long& d, unsigned long long a, unsigned long long b) {
    asm("fma.rn.f32x2 %0, %1, %2, %0;" : "+l"(d) : "l"(a), "l"(b));
}
// L2-only vector load (exchange data is produced by peer SMs each step)
__device__ __forceinline__ float4 ldcg4(const float* p) {
    float4 v;
    asm volatile("ld.global.cg.v4.f32 {%0,%1,%2,%3}, [%4];"
                 : "=f"(v.x), "=f"(v.y), "=f"(v.z), "=f"(v.w) : "l"(p));
    return v;
}
__device__ __forceinline__ unsigned ld_acquire(const unsigned* p) {
    unsigned v;
    asm volatile("ld.acquire.gpu.global.u32 %0, [%1];" : "=r"(v) : "l"(p) : "memory");
    return v;
}
__device__ __forceinline__ void st_rel(unsigned* p, unsigned v) {
    asm volatile("st.release.gpu.global.u32 [%0], %1;" :: "l"(p), "r"(v) : "memory");
}

// =====================================================================
// Phase 0: token table (biases folded), fc_W transpose, zero flags
// =====================================================================
__global__ void prep_kernel(const float* __restrict__ W_ih,
                            const float* __restrict__ b_ih,
                            const float* __restrict__ b_hh,
                            const float* __restrict__ fc_W) {
    int idx = blockIdx.x * blockDim.x + threadIdx.x;   // up to 262144
    if (idx < VOCAB * G4) {
        int v = idx >> 10;
        int r = idx & 1023;
        g_xtab[v * G4 + r] = W_ih[r * VOCAB + v] + b_ih[r] + b_hh[r];
    }
    if (idx < HID * VOCAB) {
        int k = idx >> 8;
        int c = idx & 255;
        g_fcwt[k * VOCAB + c] = fc_W[c * HID + k];
    }
    if (idx < 128) ((unsigned*)g_flag)[idx] = 0u;
}

// =====================================================================
// Phase 1: persistent LSTM recurrence (the proven R4 structure).
// 128 CTAs = 16 batch-groups (4 batches each) x 8 gate-slice members
// (32 h-indices -> 128 gate rows each). 256 threads/CTA = 128 rows x
// 2 K-chunks (128 wide). W_hh slice register-resident (w2[64]).
// h(t) exchanged through the hs region of d_out (the FC input anyway).
// Barrier: per-slice release flags (plain st.release, NO atomic RMW);
// threads 0..7 each spin on ONE flag with scalar ld.acquire (separate
// addresses -> no LTS atomic-ALU serialization), __syncthreads joins.
// =====================================================================
__global__ void __launch_bounds__(256, 1)
lstm_kernel(const int* __restrict__ x,
            const float* __restrict__ W_hh,
            float* __restrict__ out) {
    __shared__ __align__(16) float sh_h[4][2 * HPAD]; // h(t-1), skewed chunks
    __shared__ float sh_gates[128][5];                // [gate*32+j][b], padded
    __shared__ float sh_c[4][32];                     // cell state (CTA-private)
    __shared__ int   sh_tok[2][4];                    // double-buffered tokens

    const int cta    = blockIdx.x;
    const int gb     = cta >> 3;       // batch group 0..15
    const int m      = cta & 7;        // gate-slice member 0..7
    const int b_base = gb * 4;
    const int j_base = m * 32;

    const int tid  = threadIdx.x;
    const int r    = tid >> 1;         // local gate row 0..127
    const int q    = tid & 1;          // k-chunk 0..1 (128 k each)
    const int gate = r >> 5;
    const int jj   = r & 31;
    const int r_global = gate * 256 + j_base + jj;   // row of W_hh / xtab

    // --- load W_hh slice into registers as f32x2 pairs (once) ---
    unsigned long long w2[64];
    {
        const float4* wr = reinterpret_cast<const float4*>(W_hh + r_global * HID + q * 128);
#pragma unroll
        for (int i = 0; i < 32; i++) {
            float4 v = wr[i];
            w2[2 * i]     = pk2(v.x, v.y);
            w2[2 * i + 1] = pk2(v.z, v.w);
        }
    }
    if (tid < 128) sh_c[tid >> 5][tid & 31] = 0.0f;
    if (tid < 4)   sh_tok[0][tid] = x[(b_base + tid) * T_SEQ + 0] & 255;

    float* hsout = out;                                        // [B][T][H]
    float* hN    = out + (size_t)LOGITS_ELEMS;                 // [B][H]
    float* cN    = hN + BATCH * HID;                           // [B][H]

    for (int t = 0; t < T_SEQ; t++) {
        const int pb = t & 1;

        // ---- stage h(t-1) into skewed smem (L2-only loads) ----
        {
            int bb = tid >> 6, k4 = tid & 63;                  // k = k4*4
            float4 hv;
            if (t == 0) {
                hv = make_float4(0.f, 0.f, 0.f, 0.f);
            } else {
                hv = ldcg4(&hsout[((size_t)(b_base + bb) * T_SEQ + (t - 1)) * HID + k4 * 4]);
            }
            int qs = k4 >> 5, j = (k4 & 31) * 4;
            *reinterpret_cast<float4*>(&sh_h[bb][qs * HPAD + j]) = hv;
        }
        // prefetch tokens for t+1 (off the critical path)
        if (tid < 4 && t + 1 < T_SEQ)
            sh_tok[pb ^ 1][tid] = x[(b_base + tid) * T_SEQ + t + 1] & 255;
        __syncthreads();

        // ---- token-table contributions (issued early, consumed late) ----
        float xg0 = 0.f, xg1 = 0.f, xg2 = 0.f, xg3 = 0.f;
        if (q == 0) {
            xg0 = __ldg(&g_xtab[sh_tok[pb][0] * G4 + r_global]);
            xg1 = __ldg(&g_xtab[sh_tok[pb][1] * G4 + r_global]);
            xg2 = __ldg(&g_xtab[sh_tok[pb][2] * G4 + r_global]);
            xg3 = __ldg(&g_xtab[sh_tok[pb][3] * G4 + r_global]);
        }

        // ---- partial dot products: 4 batches x 128 k, weights in regs ----
        float acc[4];
#pragma unroll
        for (int bb = 0; bb < 4; bb++) {
            unsigned long long a2 = 0ull, b2 = 0ull;
            const ulonglong2* hp = reinterpret_cast<const ulonglong2*>(&sh_h[bb][q * HPAD]);
#pragma unroll
            for (int i = 0; i < 32; i++) {
                ulonglong2 hv = hp[i];
                ffma2(a2, w2[2 * i],     hv.x);
                ffma2(b2, w2[2 * i + 1], hv.y);
            }
            float a0, a1, c0, c1;
            upk2(a2, a0, a1);
            upk2(b2, c0, c1);
            acc[bb] = (a0 + a1) + (c0 + c1);
        }

        // ---- reduce across the 2 k-chunks (adjacent lanes) ----
#pragma unroll
        for (int bb = 0; bb < 4; bb++)
            acc[bb] += __shfl_xor_sync(0xffffffffu, acc[bb], 1);
        if (q == 0) {
            sh_gates[r][0] = acc[0] + xg0;
            sh_gates[r][1] = acc[1] + xg1;
            sh_gates[r][2] = acc[2] + xg2;
            sh_gates[r][3] = acc[3] + xg3;
        }
        __syncthreads();

        // ---- gate nonlinearities + state update (128 threads) ----
        if (tid < 128) {
            int bb = tid >> 5, j2 = tid & 31;
            float iv = sh_gates[j2][bb];
            float fv = sh_gates[32 + j2][bb];
            float gv = sh_gates[64 + j2][bb];
            float ov = sh_gates[96 + j2][bb];
            float is = __fdividef(1.f, 1.f + __expf(-iv));
            float fs = __fdividef(1.f, 1.f + __expf(-fv));
            float gt = 1.f - __fdividef(2.f, 1.f + __expf(2.f * gv));
            float os = __fdividef(1.f, 1.f + __expf(-ov));
            float cv = fs * sh_c[bb][j2] + is * gt;
            sh_c[bb][j2] = cv;
            float ct = 1.f - __fdividef(2.f, 1.f + __expf(2.f * cv));
            float hv = os * ct;
            hsout[((size_t)(b_base + bb) * T_SEQ + t) * HID + j_base + j2] = hv;
            if (t == T_SEQ - 1) {
                hN[(b_base + bb) * HID + j_base + j2] = hv;
                cN[(b_base + bb) * HID + j_base + j2] = cv;
            }
        }

        // ---- group barrier: release flags + distributed acquire polls ----
        __syncthreads();                       // all h stores of this CTA precede arrive
        if (t + 1 < T_SEQ) {
            if (tid == 0) st_rel(&g_flag[gb][m], (unsigned)(t + 1));
            if (tid < 8) {
                const unsigned tt = (unsigned)(t + 1);
                while (ld_acquire(&g_flag[gb][tid]) < tt) { }
            }
            __syncthreads();                   // join pollers; acquire propagates to CTA
        }
    }
}

// =====================================================================
// Phase 2: logits = hs @ fc_W^T + fc_b, in-place over the hs region.
// Each CTA: 32 rows, 128 threads, 8x8 register tile per thread, f32x2.
// =====================================================================
#define FC_KSLAB 32
#define FC_WPAD  260

__global__ void __launch_bounds__(128)
fc_kernel(float* __restrict__ out, const float* __restrict__ fc_b) {
    __shared__ __align__(16) float wslab[FC_KSLAB][FC_WPAD];  // ~33 KB
    __shared__ float sh_h[32][FC_KSLAB + 1];                  // 4.1 KB

    const int tid = threadIdx.x;
    const int rg  = tid >> 5;            // warp -> rows rg*8 .. +8
    const int cg  = tid & 31;            // cols cg*8 .. +8
    const size_t row_base = (size_t)blockIdx.x * 32;

    unsigned long long acc[8][4];
#pragma unroll
    for (int a = 0; a < 8; a++)
#pragma unroll
        for (int b = 0; b < 4; b++) acc[a][b] = 0ull;

    for (int k0 = 0; k0 < HID; k0 += FC_KSLAB) {
        __syncthreads();
        for (int i = tid; i < FC_KSLAB * 64; i += 128) {
            int kk = i >> 6, c4 = i & 63;
            *reinterpret_cast<float4*>(&wslab[kk][c4 * 4]) =
                *reinterpret_cast<const float4*>(&g_fcwt[(size_t)(k0 + kk) * VOCAB + c4 * 4]);
        }
        for (int i = tid; i < 32 * (FC_KSLAB / 4); i += 128) {
            int rr = i >> 3, k4 = i & 7;
            float4 v = *reinterpret_cast<const float4*>(
                &out[(row_base + rr) * HID + k0 + k4 * 4]);
            sh_h[rr][k4 * 4 + 0] = v.x;
            sh_h[rr][k4 * 4 + 1] = v.y;
            sh_h[rr][k4 * 4 + 2] = v.z;
            sh_h[rr][k4 * 4 + 3] = v.w;
        }
        __syncthreads();
#pragma unroll 4
        for (int kk = 0; kk < FC_KSLAB; kk++) {
            ulonglong2 wv0 = *reinterpret_cast<const ulonglong2*>(&wslab[kk][cg * 8]);
            ulonglong2 wv1 = *reinterpret_cast<const ulonglong2*>(&wslab[kk][cg * 8 + 4]);
#pragma unroll
            for (int rr = 0; rr < 8; rr++) {
                float hv = sh_h[rg * 8 + rr][kk];
                unsigned long long hp = pk2(hv, hv);
                ffma2(acc[rr][0], hp, wv0.x);
                ffma2(acc[rr][1], hp, wv0.y);
                ffma2(acc[rr][2], hp, wv1.x);
                ffma2(acc[rr][3], hp, wv1.y);
            }
        }
    }

    float bias[8];
#pragma unroll
    for (int cc = 0; cc < 8; cc++) bias[cc] = fc_b[cg * 8 + cc];
#pragma unroll
    for (int rr = 0; rr < 8; rr++) {
        float v[8];
        upk2(acc[rr][0], v[0], v[1]);
        upk2(acc[rr][1], v[2], v[3]);
        upk2(acc[rr][2], v[4], v[5]);
        upk2(acc[rr][3], v[6], v[7]);
        float4 o0 = make_float4(v[0] + bias[0], v[1] + bias[1], v[2] + bias[2], v[3] + bias[3]);
        float4 o1 = make_float4(v[4] + bias[4], v[5] + bias[5], v[6] + bias[6], v[7] + bias[7]);
        float* dst = out + (row_base + rg * 8 + rr) * VOCAB + cg * 8;
        *reinterpret_cast<float4*>(dst)     = o0;
        *reinterpret_cast<float4*>(dst + 4) = o1;
    }
}

// =====================================================================
extern "C" void kernel_launch(void* const* d_in, const int* in_sizes, int n_in,
                              void* d_out, int out_size) {
    (void)in_sizes; (void)n_in; (void)out_size;
    const int*   x      = (const int*)d_in[0];     // int32 tokens
    const float* W_ih   = (const float*)d_in[1];
    const float* W_hh   = (const float*)d_in[2];
    const float* b_ih   = (const float*)d_in[3];
    const float* b_hh   = (const float*)d_in[4];
    const float* fc_W   = (const float*)d_in[5];
    const float* fc_b   = (const float*)d_in[6];
    float* out = (float*)d_out;

    prep_kernel<<<1024, 256>>>(W_ih, b_ih, b_hh, fc_W);
    lstm_kernel<<<128, 256>>>(x, W_hh, out);
    fc_kernel<<<(BATCH * T_SEQ) / 32, 128>>>(out, fc_b);
}

// round 11
// speedup vs baseline: 3.8574x; 2.5952x over previous
#include <cuda_runtime.h>
#include <cstdint>

// TinyLSTM: B=64, T=2048, H=256, V=256
// out = [ logits (64*2048*256) | h_n (64*256) | c_n (64*256) ]  (float32)

#define T_SEQ 2048
#define BATCH 64
#define HID   256
#define G4    1024
#define VOCAB 256
#define LOGITS_ELEMS (BATCH * T_SEQ * HID)

#define CH 36      // skewed k-chunk stride (floats): chunk kq at kq*36 -> disjoint banks

// scratch (static device arrays; no allocation)
__device__ float g_xtab[VOCAB * G4];   // [v][r] = W_ih[r][v] + b_ih[r] + b_hh[r]
__device__ float g_fcwt[HID * VOCAB];  // [k][c] = fc_W[c][k]
__device__ unsigned int g_bar[16];     // per-batch-group monotonic step counters

// ---- packed f32x2 helpers ----
__device__ __forceinline__ unsigned long long pk2(float a, float b) {
    unsigned long long r;
    asm("mov.b64 %0, {%1, %2};" : "=l"(r) : "f"(a), "f"(b));
    return r;
}
__device__ __forceinline__ void upk2(unsigned long long v, float& a, float& b) {
    asm("mov.b64 {%0, %1}, %2;" : "=f"(a), "=f"(b) : "l"(v));
}
__device__ __forceinline__ void ffma2(unsigned long long& d, unsigned long long a, unsigned long long b) {
    asm("fma.rn.f32x2 %0, %1, %2, %0;" : "+l"(d) : "l"(a), "l"(b));
}
// L2-only vector load (exchange data is produced by peer SMs each step)
__device__ __forceinline__ float4 ldcg4(const float* p) {
    float4 v;
    asm volatile("ld.global.cg.v4.f32 {%0,%1,%2,%3}, [%4];"
                 : "=f"(v.x), "=f"(v.y), "=f"(v.z), "=f"(v.w) : "l"(p));
    return v;
}
__device__ __forceinline__ void red_release_add(unsigned int* p, unsigned int v) {
    asm volatile("red.release.gpu.global.add.u32 [%0], %1;" :: "l"(p), "r"(v) : "memory");
}
__device__ __forceinline__ unsigned int ld_acquire(const unsigned int* p) {
    unsigned int v;
    asm volatile("ld.acquire.gpu.global.u32 %0, [%1];" : "=r"(v) : "l"(p) : "memory");
    return v;
}

// =====================================================================
// Phase 0: token table (biases folded), fc_W transpose, reset counters
// =====================================================================
__global__ void prep_kernel(const float* __restrict__ W_ih,
                            const float* __restrict__ b_ih,
                            const float* __restrict__ b_hh,
                            const float* __restrict__ fc_W) {
    int idx = blockIdx.x * blockDim.x + threadIdx.x;
    if (idx < VOCAB * G4) {
        int v = idx >> 10;
        int r = idx & 1023;
        g_xtab[v * G4 + r] = W_ih[r * VOCAB + v] + b_ih[r] + b_hh[r];
    }
    if (idx < HID * VOCAB) {
        int k = idx >> 8;
        int c = idx & 255;
        g_fcwt[k * VOCAB + c] = fc_W[c * HID + k];
    }
    if (idx < 16) g_bar[idx] = 0u;
}

// =====================================================================
// Phase 1: persistent LSTM recurrence.
// 128 CTAs = 16 batch-groups (4 batches) x 8 gate-slice members (32 j
// columns of all 4 gates). 256 threads = 32 j x 8 k-chunks (32 k each).
// FUSED layout: each thread holds its j's 4 gate rows over its k-chunk
// in registers (w2[64] = 128 regs) and all 16 (gate,batch) accumulators;
// reduce over the 8 k-chunks via 16 shuffles (pair-redundant result),
// epilogue inline with cell state in a register -> no gates smem round
// trip; 3 syncthreads/step instead of 4.
// Exchange/barrier: EXACTLY the proven R4 mechanism — h through the hs
// region of d_out; red.release.gpu.add on one per-group counter, tid0
// ld.acquire poll, target 8*(t+1).
// =====================================================================
__global__ void __launch_bounds__(256, 1)
lstm_kernel(const int* __restrict__ x,
            const float* __restrict__ W_hh,
            float* __restrict__ out) {
    __shared__ __align__(16) float sh_h[4][8 * CH];  // h(t-1): [batch][chunk*CH + j]
    __shared__ int sh_tok[2][4];                     // double-buffered tokens

    const int cta    = blockIdx.x;
    const int gb     = cta >> 3;       // batch group 0..15
    const int m      = cta & 7;        // gate-slice member 0..7
    const int b_base = gb * 4;
    const int j_base = m * 32;

    const int tid = threadIdx.x;
    const int j   = tid >> 3;          // local column 0..31
    const int kq  = tid & 7;           // k-chunk 0..7 (32 k each)
    const int bmy = kq >> 1;           // epilogue batch owned by this thread
    const int row0 = j_base + j;       // gate-0 row; gate g at row0 + g*256

    // --- W_hh slice -> registers: 4 gates x 32 k = 64 f32x2 (128 regs) ---
    unsigned long long w2[64];
#pragma unroll
    for (int g = 0; g < 4; g++) {
        const float4* wr = reinterpret_cast<const float4*>(
            W_hh + (size_t)(g * 256 + row0) * HID + kq * 32);
#pragma unroll
        for (int i = 0; i < 8; i++) {
            float4 v = wr[i];
            w2[g * 16 + 2 * i]     = pk2(v.x, v.y);
            w2[g * 16 + 2 * i + 1] = pk2(v.z, v.w);
        }
    }
    float creg = 0.0f;                 // cell state for (bmy, row0); pair-redundant
    if (tid < 4) sh_tok[0][tid] = x[(size_t)(b_base + tid) * T_SEQ + 0] & 255;

    float* hsout = out;                                 // [B][T][H]
    float* hN    = out + (size_t)LOGITS_ELEMS;          // [B][H]
    float* cN    = hN + BATCH * HID;                    // [B][H]
    unsigned int* bar = &g_bar[gb];

    for (int t = 0; t < T_SEQ; t++) {
        const int pb = t & 1;

        // ---- stage h(t-1) into skewed smem (L2-only loads) ----
        {
            int bb = tid >> 6, k4 = tid & 63;           // k = k4*4
            float4 hv;
            if (t == 0) {
                hv = make_float4(0.f, 0.f, 0.f, 0.f);
            } else {
                hv = ldcg4(&hsout[((size_t)(b_base + bb) * T_SEQ + (t - 1)) * HID + k4 * 4]);
            }
            *reinterpret_cast<float4*>(&sh_h[bb][(k4 >> 3) * CH + (k4 & 7) * 4]) = hv;
        }
        // prefetch tokens for t+1 (off the critical path)
        if (tid < 4 && t + 1 < T_SEQ)
            sh_tok[pb ^ 1][tid] = x[(size_t)(b_base + tid) * T_SEQ + t + 1] & 255;
        __syncthreads();

        // ---- token-table contributions for this thread's batch (early issue) ----
        const int tok = sh_tok[pb][bmy];
        float xg[4];
#pragma unroll
        for (int g = 0; g < 4; g++)
            xg[g] = __ldg(&g_xtab[tok * G4 + g * 256 + row0]);

        // ---- matmul: 4 gates x 4 batches x 32 k, weights in registers ----
        unsigned long long acc2[4][4];
#pragma unroll
        for (int g = 0; g < 4; g++)
#pragma unroll
            for (int b = 0; b < 4; b++) acc2[g][b] = 0ull;

#pragma unroll
        for (int b = 0; b < 4; b++) {
            const ulonglong2* hp =
                reinterpret_cast<const ulonglong2*>(&sh_h[b][kq * CH]);
#pragma unroll
            for (int i = 0; i < 8; i++) {
                ulonglong2 hv = hp[i];
#pragma unroll
                for (int g = 0; g < 4; g++) {
                    ffma2(acc2[g][b], w2[g * 16 + 2 * i],     hv.x);
                    ffma2(acc2[g][b], w2[g * 16 + 2 * i + 1], hv.y);
                }
            }
        }

        // ---- horizontal sums ----
        float af[4][4];
#pragma unroll
        for (int g = 0; g < 4; g++)
#pragma unroll
            for (int b = 0; b < 4; b++) {
                float a0, a1;
                upk2(acc2[g][b], a0, a1);
                af[g][b] = a0 + a1;
            }

        // ---- reduce-scatter over the 8 k-chunks (proven in R7/R8 core) ----
        const bool lo = (kq < 4);
        float a2[4][2];
#pragma unroll
        for (int g = 0; g < 4; g++) {
            float s0 = lo ? af[g][2] : af[g][0];
            float s1 = lo ? af[g][3] : af[g][1];
            s0 = __shfl_xor_sync(0xffffffffu, s0, 4);
            s1 = __shfl_xor_sync(0xffffffffu, s1, 4);
            a2[g][0] = (lo ? af[g][0] : af[g][2]) + s0;
            a2[g][1] = (lo ? af[g][1] : af[g][3]) + s1;
        }
        const bool sel = (kq & 2);
        float fin[4];
#pragma unroll
        for (int g = 0; g < 4; g++) {
            float s = sel ? a2[g][0] : a2[g][1];
            s = __shfl_xor_sync(0xffffffffu, s, 2);
            fin[g] = (sel ? a2[g][1] : a2[g][0]) + s;
        }
#pragma unroll
        for (int g = 0; g < 4; g++)
            fin[g] += __shfl_xor_sync(0xffffffffu, fin[g], 1);
        // both lanes of each pair now hold full i,f,g,o for batch bmy, column j

        // ---- epilogue inline (pair-redundant; odd lane stores) ----
        {
            float iv = fin[0] + xg[0];
            float fv = fin[1] + xg[1];
            float gv = fin[2] + xg[2];
            float ov = fin[3] + xg[3];
            float is = __fdividef(1.f, 1.f + __expf(-iv));
            float fs = __fdividef(1.f, 1.f + __expf(-fv));
            float gt = 1.f - __fdividef(2.f, 1.f + __expf(2.f * gv));
            float os = __fdividef(1.f, 1.f + __expf(-ov));
            creg = fs * creg + is * gt;
            float ct = 1.f - __fdividef(2.f, 1.f + __expf(2.f * creg));
            float hv = os * ct;
            if (kq & 1) {
                hsout[((size_t)(b_base + bmy) * T_SEQ + t) * HID + row0] = hv;
                if (t == T_SEQ - 1) {
                    hN[(b_base + bmy) * HID + row0] = hv;
                    cN[(b_base + bmy) * HID + row0] = creg;
                }
            }
        }

        // ---- group barrier: EXACT R4 mechanism ----
        if (t + 1 < T_SEQ) {
            __syncthreads();                   // all h stores precede arrive
            if (tid == 0) {
                red_release_add(bar, 1u);
                const unsigned int target = 8u * (unsigned int)(t + 1);
                while (ld_acquire(bar) < target) { }
            }
            __syncthreads();                   // acquire propagates to all threads
        }
    }
}

// =====================================================================
// Phase 2: logits = hs @ fc_W^T + fc_b, in-place over the hs region.
// Each CTA: 32 rows, 128 threads, 8x8 register tile per thread, f32x2.
// =====================================================================
#define FC_KSLAB 32
#define FC_WPAD  260

__global__ void __launch_bounds__(128)
fc_kernel(float* __restrict__ out, const float* __restrict__ fc_b) {
    __shared__ __align__(16) float wslab[FC_KSLAB][FC_WPAD];  // ~33 KB
    __shared__ float sh_h[32][FC_KSLAB + 1];                  // 4.1 KB

    const int tid = threadIdx.x;
    const int rg  = tid >> 5;
    const int cg  = tid & 31;
    const size_t row_base = (size_t)blockIdx.x * 32;

    unsigned long long acc[8][4];
#pragma unroll
    for (int a = 0; a < 8; a++)
#pragma unroll
        for (int b = 0; b < 4; b++) acc[a][b] = 0ull;

    for (int k0 = 0; k0 < HID; k0 += FC_KSLAB) {
        __syncthreads();
        for (int i = tid; i < FC_KSLAB * 64; i += 128) {
            int kk = i >> 6, c4 = i & 63;
            *reinterpret_cast<float4*>(&wslab[kk][c4 * 4]) =
                *reinterpret_cast<const float4*>(&g_fcwt[(size_t)(k0 + kk) * VOCAB + c4 * 4]);
        }
        for (int i = tid; i < 32 * (FC_KSLAB / 4); i += 128) {
            int rr = i >> 3, k4 = i & 7;
            float4 v = *reinterpret_cast<const float4*>(
                &out[(row_base + rr) * HID + k0 + k4 * 4]);
            sh_h[rr][k4 * 4 + 0] = v.x;
            sh_h[rr][k4 * 4 + 1] = v.y;
            sh_h[rr][k4 * 4 + 2] = v.z;
            sh_h[rr][k4 * 4 + 3] = v.w;
        }
        __syncthreads();
#pragma unroll 4
        for (int kk = 0; kk < FC_KSLAB; kk++) {
            ulonglong2 wv0 = *reinterpret_cast<const ulonglong2*>(&wslab[kk][cg * 8]);
            ulonglong2 wv1 = *reinterpret_cast<const ulonglong2*>(&wslab[kk][cg * 8 + 4]);
#pragma unroll
            for (int rr = 0; rr < 8; rr++) {
                float hv = sh_h[rg * 8 + rr][kk];
                unsigned long long hp = pk2(hv, hv);
                ffma2(acc[rr][0], hp, wv0.x);
                ffma2(acc[rr][1], hp, wv0.y);
                ffma2(acc[rr][2], hp, wv1.x);
                ffma2(acc[rr][3], hp, wv1.y);
            }
        }
    }

    float bias[8];
#pragma unroll
    for (int cc = 0; cc < 8; cc++) bias[cc] = fc_b[cg * 8 + cc];
#pragma unroll
    for (int rr = 0; rr < 8; rr++) {
        float v[8];
        upk2(acc[rr][0], v[0], v[1]);
        upk2(acc[rr][1], v[2], v[3]);
        upk2(acc[rr][2], v[4], v[5]);
        upk2(acc[rr][3], v[6], v[7]);
        float4 o0 = make_float4(v[0] + bias[0], v[1] + bias[1], v[2] + bias[2], v[3] + bias[3]);
        float4 o1 = make_float4(v[4] + bias[4], v[5] + bias[5], v[6] + bias[6], v[7] + bias[7]);
        float* dst = out + (row_base + rg * 8 + rr) * VOCAB + cg * 8;
        *reinterpret_cast<float4*>(dst)     = o0;
        *reinterpret_cast<float4*>(dst + 4) = o1;
    }
}

// =====================================================================
extern "C" void kernel_launch(void* const* d_in, const int* in_sizes, int n_in,
                              void* d_out, int out_size) {
    (void)in_sizes; (void)n_in; (void)out_size;
    const int*   x      = (const int*)d_in[0];     // int32 tokens
    const float* W_ih   = (const float*)d_in[1];
    const float* W_hh   = (const float*)d_in[2];
    const float* b_ih   = (const float*)d_in[3];
    const float* b_hh   = (const float*)d_in[4];
    const float* fc_W   = (const float*)d_in[5];
    const float* fc_b   = (const float*)d_in[6];
    float* out = (float*)d_out;

    prep_kernel<<<1024, 256>>>(W_ih, b_ih, b_hh, fc_W);
    lstm_kernel<<<128, 256>>>(x, W_hh, out);
    fc_kernel<<<(BATCH * T_SEQ) / 32, 128>>>(out, fc_b);
}

// round 12
// speedup vs baseline: 4.1948x; 1.0875x over previous
#include <cuda_runtime.h>
#include <cstdint>

// TinyLSTM: B=64, T=2048, H=256, V=256
// out = [ logits (64*2048*256) | h_n (64*256) | c_n (64*256) ]  (float32)

#define T_SEQ 2048
#define BATCH 64
#define HID   256
#define G4    1024
#define VOCAB 256
#define LOGITS_ELEMS (BATCH * T_SEQ * HID)

#define CH 36       // skewed k-chunk stride (floats): chunk kq at kq*36 -> disjoint banks
#define N_TILES 4096u   // 64 t-chunks x 64 batches (32 rows each)

// scratch (static device arrays; no allocation)
__device__ float g_xtab[VOCAB * G4];   // [v][r] = W_ih[r][v] + b_ih[r] + b_hh[r]
__device__ float g_fcwt[HID * VOCAB];  // [k][c] = fc_W[c][k]
__device__ unsigned int g_bar[16];     // per-batch-group monotonic step counters
__device__ unsigned int g_ticket;      // FC tile ticket counter

// ---- packed f32x2 helpers ----
__device__ __forceinline__ unsigned long long pk2(float a, float b) {
    unsigned long long r;
    asm("mov.b64 %0, {%1, %2};" : "=l"(r) : "f"(a), "f"(b));
    return r;
}
__device__ __forceinline__ void upk2(unsigned long long v, float& a, float& b) {
    asm("mov.b64 {%0, %1}, %2;" : "=f"(a), "=f"(b) : "l"(v));
}
__device__ __forceinline__ void ffma2(unsigned long long& d, unsigned long long a, unsigned long long b) {
    asm("fma.rn.f32x2 %0, %1, %2, %0;" : "+l"(d) : "l"(a), "l"(b));
}
__device__ __forceinline__ float4 ldcg4(const float* p) {
    float4 v;
    asm volatile("ld.global.cg.v4.f32 {%0,%1,%2,%3}, [%4];"
                 : "=f"(v.x), "=f"(v.y), "=f"(v.z), "=f"(v.w) : "l"(p));
    return v;
}
__device__ __forceinline__ void red_release_add(unsigned int* p, unsigned int v) {
    asm volatile("red.release.gpu.global.add.u32 [%0], %1;" :: "l"(p), "r"(v) : "memory");
}
__device__ __forceinline__ unsigned int ld_acquire(const unsigned int* p) {
    unsigned int v;
    asm volatile("ld.acquire.gpu.global.u32 %0, [%1];" : "=r"(v) : "l"(p) : "memory");
    return v;
}

// =====================================================================
// Phase 0: token table (biases folded), fc_W transpose, reset counters
// =====================================================================
__global__ void prep_kernel(const float* __restrict__ W_ih,
                            const float* __restrict__ b_ih,
                            const float* __restrict__ b_hh,
                            const float* __restrict__ fc_W) {
    int idx = blockIdx.x * blockDim.x + threadIdx.x;
    if (idx < VOCAB * G4) {
        int v = idx >> 10;
        int r = idx & 1023;
        g_xtab[v * G4 + r] = W_ih[r * VOCAB + v] + b_ih[r] + b_hh[r];
    }
    if (idx < HID * VOCAB) {
        int k = idx >> 8;
        int c = idx & 255;
        g_fcwt[k * VOCAB + c] = fc_W[c * HID + k];
    }
    if (idx < 16) g_bar[idx] = 0u;
    if (idx == 16) g_ticket = 0u;
}

// =====================================================================
// Shared-memory union: LSTM view / FC-tile view (both < 48 KB static)
// =====================================================================
#define FC_WPAD 260
union SMemU {
    struct {
        float sh_h[4][8 * CH];     // h(t-1): [batch][chunk*CH + j]
        int   sh_tok[2][4];        // double-buffered tokens
    } l;
    struct {
        float w[32][FC_WPAD];      // weight k-slab  (~33 KB)
        float h[32][33];           // h rows k-slab  (~4.2 KB)
    } f;
};

// =====================================================================
// FC tile: 32 rows x 256 cols, 256 threads, 4x8 register tile, f32x2.
// In-place over the hs region (reads all k-slabs before storing).
// =====================================================================
__device__ __forceinline__ void fc_tile(float* __restrict__ sw,   // [32][FC_WPAD]
                                        float* __restrict__ shh,  // [32][33]
                                        float* __restrict__ out,
                                        const float* __restrict__ fc_b,
                                        size_t row_base, int tid) {
    const int rg = tid >> 5;          // 0..7 -> rows rg*4 .. +4
    const int cg = tid & 31;          // cols cg*8 .. +8

    unsigned long long acc[4][4];
#pragma unroll
    for (int a = 0; a < 4; a++)
#pragma unroll
        for (int b = 0; b < 4; b++) acc[a][b] = 0ull;

    for (int k0 = 0; k0 < HID; k0 += 32) {
        __syncthreads();              // also joins the tid0 dependency spin
        // weight slab: 32 k x 256 c (2048 float4, 8 per thread)
        for (int i = tid; i < 32 * 64; i += 256) {
            int kk = i >> 6, c4 = i & 63;
            *reinterpret_cast<float4*>(&sw[kk * FC_WPAD + c4 * 4]) =
                *reinterpret_cast<const float4*>(&g_fcwt[(size_t)(k0 + kk) * VOCAB + c4 * 4]);
        }
        // h slab: 32 rows x 32 k (256 float4, 1 per thread)
        {
            int rr = tid >> 3, k4 = tid & 7;
            float4 v = *reinterpret_cast<const float4*>(
                &out[(row_base + rr) * HID + k0 + k4 * 4]);
            shh[rr * 33 + k4 * 4 + 0] = v.x;
            shh[rr * 33 + k4 * 4 + 1] = v.y;
            shh[rr * 33 + k4 * 4 + 2] = v.z;
            shh[rr * 33 + k4 * 4 + 3] = v.w;
        }
        __syncthreads();
#pragma unroll 4
        for (int kk = 0; kk < 32; kk++) {
            ulonglong2 wv0 = *reinterpret_cast<const ulonglong2*>(&sw[kk * FC_WPAD + cg * 8]);
            ulonglong2 wv1 = *reinterpret_cast<const ulonglong2*>(&sw[kk * FC_WPAD + cg * 8 + 4]);
#pragma unroll
            for (int rr = 0; rr < 4; rr++) {
                float hv = shh[(rg * 4 + rr) * 33 + kk];
                unsigned long long hp = pk2(hv, hv);
                ffma2(acc[rr][0], hp, wv0.x);
                ffma2(acc[rr][1], hp, wv0.y);
                ffma2(acc[rr][2], hp, wv1.x);
                ffma2(acc[rr][3], hp, wv1.y);
            }
        }
    }

    float bias[8];
#pragma unroll
    for (int cc = 0; cc < 8; cc++) bias[cc] = __ldg(&fc_b[cg * 8 + cc]);
#pragma unroll
    for (int rr = 0; rr < 4; rr++) {
        float v[8];
        upk2(acc[rr][0], v[0], v[1]);
        upk2(acc[rr][1], v[2], v[3]);
        upk2(acc[rr][2], v[4], v[5]);
        upk2(acc[rr][3], v[6], v[7]);
        float4 o0 = make_float4(v[0] + bias[0], v[1] + bias[1], v[2] + bias[2], v[3] + bias[3]);
        float4 o1 = make_float4(v[4] + bias[4], v[5] + bias[5], v[6] + bias[6], v[7] + bias[7]);
        float* dst = out + (row_base + rg * 4 + rr) * VOCAB + cg * 8;
        *reinterpret_cast<float4*>(dst)     = o0;
        *reinterpret_cast<float4*>(dst + 4) = o1;
    }
}

// =====================================================================
// Fused kernel, grid 148 (1 CTA/SM):
//   CTA 0..127 : persistent LSTM (R11-proven path), then join FC pool.
//   CTA 128..147: FC workers from t=0 on the 20 LSTM-free SMs.
// FC tiles (32 rows = one batch x 32 timesteps) are pulled from a global
// ticket counter in time-major order; each tile spins until its group's
// counter covers step 32*tc+32 (the +1 step guarantees the LSTM already
// STAGED row 32*tc+31, making the in-place logits overwrite WAR-safe).
// =====================================================================
__global__ void __launch_bounds__(256, 1)
fused_kernel(const int* __restrict__ x,
             const float* __restrict__ W_hh,
             float* __restrict__ out,
             const float* __restrict__ fc_b) {
    __shared__ SMemU sm;
    __shared__ unsigned sh_tix;

    const int cta = blockIdx.x;
    const int tid = threadIdx.x;
    float* hsout = out;                                 // [B][T][H]

    if (cta < 128) {
        // ================= LSTM phase (proven R11 structure) =================
        const int gb     = cta >> 3;       // batch group 0..15
        const int m      = cta & 7;        // gate-slice member 0..7
        const int b_base = gb * 4;
        const int j_base = m * 32;

        const int j   = tid >> 3;          // local column 0..31
        const int kq  = tid & 7;           // k-chunk 0..7 (32 k each)
        const int bmy = kq >> 1;           // epilogue batch owned by this thread
        const int row0 = j_base + j;       // gate-0 row; gate g at row0 + g*256

        unsigned long long w2[64];
#pragma unroll
        for (int g = 0; g < 4; g++) {
            const float4* wr = reinterpret_cast<const float4*>(
                W_hh + (size_t)(g * 256 + row0) * HID + kq * 32);
#pragma unroll
            for (int i = 0; i < 8; i++) {
                float4 v = wr[i];
                w2[g * 16 + 2 * i]     = pk2(v.x, v.y);
                w2[g * 16 + 2 * i + 1] = pk2(v.z, v.w);
            }
        }
        float creg = 0.0f;
        if (tid < 4) sm.l.sh_tok[0][tid] = x[(size_t)(b_base + tid) * T_SEQ + 0] & 255;

        float* hN = out + (size_t)LOGITS_ELEMS;
        float* cN = hN + BATCH * HID;
        unsigned int* bar = &g_bar[gb];

        for (int t = 0; t < T_SEQ; t++) {
            const int pb = t & 1;

            // stage h(t-1) into skewed smem (L2-only loads)
            {
                int bb = tid >> 6, k4 = tid & 63;
                float4 hv;
                if (t == 0) {
                    hv = make_float4(0.f, 0.f, 0.f, 0.f);
                } else {
                    hv = ldcg4(&hsout[((size_t)(b_base + bb) * T_SEQ + (t - 1)) * HID + k4 * 4]);
                }
                *reinterpret_cast<float4*>(&sm.l.sh_h[bb][(k4 >> 3) * CH + (k4 & 7) * 4]) = hv;
            }
            if (tid < 4 && t + 1 < T_SEQ)
                sm.l.sh_tok[pb ^ 1][tid] = x[(size_t)(b_base + tid) * T_SEQ + t + 1] & 255;
            __syncthreads();

            // token-table contributions (early issue)
            const int tok = sm.l.sh_tok[pb][bmy];
            float xg[4];
#pragma unroll
            for (int g = 0; g < 4; g++)
                xg[g] = __ldg(&g_xtab[tok * G4 + g * 256 + row0]);

            // matmul: 4 gates x 4 batches x 32 k, weights in registers
            unsigned long long acc2[4][4];
#pragma unroll
            for (int g = 0; g < 4; g++)
#pragma unroll
                for (int b = 0; b < 4; b++) acc2[g][b] = 0ull;
#pragma unroll
            for (int b = 0; b < 4; b++) {
                const ulonglong2* hp =
                    reinterpret_cast<const ulonglong2*>(&sm.l.sh_h[b][kq * CH]);
#pragma unroll
                for (int i = 0; i < 8; i++) {
                    ulonglong2 hv = hp[i];
#pragma unroll
                    for (int g = 0; g < 4; g++) {
                        ffma2(acc2[g][b], w2[g * 16 + 2 * i],     hv.x);
                        ffma2(acc2[g][b], w2[g * 16 + 2 * i + 1], hv.y);
                    }
                }
            }

            // horizontal sums
            float af[4][4];
#pragma unroll
            for (int g = 0; g < 4; g++)
#pragma unroll
                for (int b = 0; b < 4; b++) {
                    float a0, a1;
                    upk2(acc2[g][b], a0, a1);
                    af[g][b] = a0 + a1;
                }

            // reduce-scatter over the 8 k-chunks
            const bool lo = (kq < 4);
            float a2[4][2];
#pragma unroll
            for (int g = 0; g < 4; g++) {
                float s0 = lo ? af[g][2] : af[g][0];
                float s1 = lo ? af[g][3] : af[g][1];
                s0 = __shfl_xor_sync(0xffffffffu, s0, 4);
                s1 = __shfl_xor_sync(0xffffffffu, s1, 4);
                a2[g][0] = (lo ? af[g][0] : af[g][2]) + s0;
                a2[g][1] = (lo ? af[g][1] : af[g][3]) + s1;
            }
            const bool sel = (kq & 2);
            float fin[4];
#pragma unroll
            for (int g = 0; g < 4; g++) {
                float s = sel ? a2[g][0] : a2[g][1];
                s = __shfl_xor_sync(0xffffffffu, s, 2);
                fin[g] = (sel ? a2[g][1] : a2[g][0]) + s;
            }
#pragma unroll
            for (int g = 0; g < 4; g++)
                fin[g] += __shfl_xor_sync(0xffffffffu, fin[g], 1);

            // epilogue inline (pair-redundant; odd lane stores)
            {
                float iv = fin[0] + xg[0];
                float fv = fin[1] + xg[1];
                float gv = fin[2] + xg[2];
                float ov = fin[3] + xg[3];
                float is = __fdividef(1.f, 1.f + __expf(-iv));
                float fs = __fdividef(1.f, 1.f + __expf(-fv));
                float gt = 1.f - __fdividef(2.f, 1.f + __expf(2.f * gv));
                float os = __fdividef(1.f, 1.f + __expf(-ov));
                creg = fs * creg + is * gt;
                float ct = 1.f - __fdividef(2.f, 1.f + __expf(2.f * creg));
                float hv = os * ct;
                if (kq & 1) {
                    hsout[((size_t)(b_base + bmy) * T_SEQ + t) * HID + row0] = hv;
                    if (t == T_SEQ - 1) {
                        hN[(b_base + bmy) * HID + row0] = hv;
                        cN[(b_base + bmy) * HID + row0] = creg;
                    }
                }
            }

            // group barrier (proven R4 mechanism)
            if (t + 1 < T_SEQ) {
                __syncthreads();
                if (tid == 0) {
                    red_release_add(bar, 1u);
                    const unsigned int target = 8u * (unsigned int)(t + 1);
                    while (ld_acquire(bar) < target) { }
                }
                __syncthreads();
            }
        }
        // final release so counters reach 8*2048 (consumed by FC deps)
        __syncthreads();
        if (tid == 0) red_release_add(bar, 1u);
    }

    // ================= FC worker pool (all 148 CTAs end up here) =========
    for (;;) {
        __syncthreads();                       // protect sh_tix + smem reuse
        if (tid == 0) sh_tix = atomicAdd(&g_ticket, 1u);
        __syncthreads();
        unsigned tix = sh_tix;
        if (tix >= N_TILES) break;
        int tc = (int)(tix >> 6);              // t-chunk 0..63 (time-major order)
        int b  = (int)(tix & 63u);             // batch 0..63
        // WAR-safe dep: group completed step 32*tc+32 (its staging already
        // consumed row 32*tc+31). Counter is 8*(steps completed).
        unsigned need = 8u * (32u * (unsigned)tc + 33u);
        if (need > 8u * (unsigned)T_SEQ) need = 8u * (unsigned)T_SEQ;
        if (tid == 0) {
            while (ld_acquire(&g_bar[b >> 2]) < need) { }
        }
        // fc_tile's first __syncthreads joins the spin before any h load
        fc_tile(&sm.f.w[0][0], &sm.f.h[0][0], out, fc_b,
                (size_t)b * T_SEQ + (size_t)(32 * tc), tid);
    }
}

// =====================================================================
extern "C" void kernel_launch(void* const* d_in, const int* in_sizes, int n_in,
                              void* d_out, int out_size) {
    (void)in_sizes; (void)n_in; (void)out_size;
    const int*   x      = (const int*)d_in[0];     // int32 tokens
    const float* W_ih   = (const float*)d_in[1];
    const float* W_hh   = (const float*)d_in[2];
    const float* b_ih   = (const float*)d_in[3];
    const float* b_hh   = (const float*)d_in[4];
    const float* fc_W   = (const float*)d_in[5];
    const float* fc_b   = (const float*)d_in[6];
    float* out = (float*)d_out;

    prep_kernel<<<1024, 256>>>(W_ih, b_ih, b_hh, fc_W);
    fused_kernel<<<148, 256>>>(x, W_hh, out, fc_b);
}